// round 8
// baseline (speedup 1.0000x reference)
#include <cuda_runtime.h>
#include <math.h>

// Problem dims
#define B_ 8
#define L_ 512
#define D_ 512
#define H_ 8
#define DH_ 64
#define NROWS 4096          // B*L
#define NPAD 1664           // 512(q)+512(k)+512(v)+24(p) padded

// Output layout (concatenated fp32): readout | state_seq | mom_seq
#define OFF_S 2097152UL
#define OFF_M 136314880UL

// Packed per-(b,h) stream: [q(64) | k_norm(64) | v(64) | gates(4)] per step
#define PSTEP 196

// Scratch (static device arrays — no allocation)
__device__ float g_W[D_ * NPAD];                       // packed [Wq|Wk|Wv|Wp|0pad]
__device__ float g_out[(size_t)NROWS * NPAD];          // raw projections
__device__ float g_pack[(size_t)B_ * H_ * L_ * PSTEP]; // packed recurrence stream

// ---------------------------------------------------------------------------
// Kernel 1: pack weights into one [512 x 1664] matrix (zero-padded)
// ---------------------------------------------------------------------------
__global__ void pack_weights_kernel(const float* __restrict__ Wq,
                                    const float* __restrict__ Wk,
                                    const float* __restrict__ Wv,
                                    const float* __restrict__ Wp) {
    int idx = blockIdx.x * blockDim.x + threadIdx.x;
    if (idx >= D_ * NPAD) return;
    int d = idx / NPAD;
    int n = idx - d * NPAD;
    float v = 0.f;
    if (n < 512)       v = Wq[d * 512 + n];
    else if (n < 1024) v = Wk[d * 512 + (n - 512)];
    else if (n < 1536) v = Wv[d * 512 + (n - 1024)];
    else if (n < 1560) v = Wp[d * 24 + (n - 1536)];
    g_W[idx] = v;
}

// ---------------------------------------------------------------------------
// Kernel 2: SGEMM  C[4096,1664] = A[4096,512] * W[512,1664]
// 128x128 tile, BK=8, 256 threads, 8x8 per thread.
// Inner product uses packed fp32x2 FMA (fma.rn.f32x2): acc pairs along N,
// B pairs loaded pre-packed from smem, A scalar duplicated via mov.b64.
// Bit-exact vs scalar FFMA (IEEE fp32 per lane).
// ---------------------------------------------------------------------------
__global__ __launch_bounds__(256) void sgemm_kernel(const float* __restrict__ A) {
    __shared__ float As[8][128];
    __shared__ float Bs[8][128];
    const int tid  = threadIdx.x;
    const int brow = blockIdx.y * 128;
    const int bcol = blockIdx.x * 128;
    const int arow = tid >> 1, acol = (tid & 1) * 4;
    const int bro  = tid >> 5, bco  = (tid & 31) * 4;
    const int tx   = tid & 15, ty   = tid >> 4;

    // acc pairs: accp[i][j] = packed {C(i,2j), C(i,2j+1)}
    unsigned long long accp[8][4];
#pragma unroll
    for (int i = 0; i < 8; i++)
#pragma unroll
        for (int j = 0; j < 4; j++) accp[i][j] = 0ULL;

    const float* Ap = A + (size_t)(brow + arow) * D_ + acol;
    const float* Bp = g_W + (size_t)bro * NPAD + bcol + bco;

    for (int k0 = 0; k0 < D_; k0 += 8) {
        float4 av = *(const float4*)Ap;
        float4 bv = *(const float4*)Bp;
        As[acol + 0][arow] = av.x;
        As[acol + 1][arow] = av.y;
        As[acol + 2][arow] = av.z;
        As[acol + 3][arow] = av.w;
        *(float4*)&Bs[bro][bco] = bv;
        __syncthreads();
#pragma unroll
        for (int kk = 0; kk < 8; kk++) {
            float ra[8];
            *(float4*)&ra[0] = *(const float4*)&As[kk][ty * 8];
            *(float4*)&ra[4] = *(const float4*)&As[kk][ty * 8 + 4];
            // B pairs come out of smem already packed (little-endian: low = even col)
            unsigned long long bp[4];
            {
                const double2* bq = (const double2*)&Bs[kk][tx * 8];
                double2 b01 = bq[0];
                double2 b23 = bq[1];
                bp[0] = __double_as_longlong(b01.x);
                bp[1] = __double_as_longlong(b01.y);
                bp[2] = __double_as_longlong(b23.x);
                bp[3] = __double_as_longlong(b23.y);
            }
#pragma unroll
            for (int i = 0; i < 8; i++) {
                unsigned long long ad;
                asm("mov.b64 %0, {%1, %1};" : "=l"(ad) : "f"(ra[i]));
#pragma unroll
                for (int j = 0; j < 4; j++) {
                    asm("fma.rn.f32x2 %0, %1, %2, %0;"
                        : "+l"(accp[i][j]) : "l"(ad), "l"(bp[j]));
                }
            }
        }
        __syncthreads();
        Ap += 8;
        Bp += 8 * NPAD;
    }

    float* Cp = g_out + (size_t)(brow + ty * 8) * NPAD + bcol + tx * 8;
#pragma unroll
    for (int i = 0; i < 8; i++) {
        // accp[i][0..3] reinterpreted as 8 consecutive floats (pairs are N-adjacent)
        const float* af = (const float*)&accp[i][0];
        *(float4*)(Cp + 0) = make_float4(af[0], af[1], af[2], af[3]);
        *(float4*)(Cp + 4) = make_float4(af[4], af[5], af[6], af[7]);
        Cp += NPAD;
    }
}

// ---------------------------------------------------------------------------
// Kernel 3: postproc — normalize k, compute gates, repack into per-(b,h)
// contiguous stream g_pack[b][h][l] = [q64 | k64 | v64 | a,e,th,0]
// ---------------------------------------------------------------------------
__global__ __launch_bounds__(64) void postproc_kernel(const float* __restrict__ bp) {
    const int row = blockIdx.x;
    const int b = row >> 9, l = row & 511;
    const float* base = g_out + (size_t)row * NPAD;
    const int t  = threadIdx.x;
    const int hh = t >> 3, e8 = t & 7;

    __shared__ float sg[24];
    if (t < 24) {
        float p = base[1536 + t] + bp[t];
        sg[t] = (t < 16) ? (1.0f / (1.0f + expf(-p)))
                         : ((p > 20.f) ? p : log1pf(expf(p)));
    }

    float* dst = g_pack + ((size_t)(b * 8 + hh) * 512 + l) * PSTEP;

    // k: normalize and write
    float kv[8];
    const float* kb = base + 512 + hh * 64 + e8 * 8;
    *(float4*)&kv[0] = *(const float4*)(kb + 0);
    *(float4*)&kv[4] = *(const float4*)(kb + 4);
    float ss = 0.f;
#pragma unroll
    for (int u = 0; u < 8; u++) ss = fmaf(kv[u], kv[u], ss);
    ss += __shfl_xor_sync(0xffffffffu, ss, 1);
    ss += __shfl_xor_sync(0xffffffffu, ss, 2);
    ss += __shfl_xor_sync(0xffffffffu, ss, 4);
    float scale = 1.0f / fmaxf(sqrtf(ss), 1e-12f);
#pragma unroll
    for (int u = 0; u < 8; u++) kv[u] *= scale;
    *(float4*)(dst + 64 + e8 * 8 + 0) = *(float4*)&kv[0];
    *(float4*)(dst + 64 + e8 * 8 + 4) = *(float4*)&kv[4];

    // q copy
    const float* qb = base + hh * 64 + e8 * 8;
    *(float4*)(dst + e8 * 8 + 0) = *(const float4*)(qb + 0);
    *(float4*)(dst + e8 * 8 + 4) = *(const float4*)(qb + 4);

    // v copy
    const float* vb = base + 1024 + hh * 64 + e8 * 8;
    *(float4*)(dst + 128 + e8 * 8 + 0) = *(const float4*)(vb + 0);
    *(float4*)(dst + 128 + e8 * 8 + 4) = *(const float4*)(vb + 4);

    __syncthreads();
    if (e8 < 4) dst[192 + e8] = (e8 < 3) ? sg[e8 * 8 + hh] : 0.f;
}

// ---------------------------------------------------------------------------
// Kernel 4: recurrence (round-5 proven config).
// grid = B*H*16 = 1024 CTAs x 64 threads (2048 warps).
// CTA handles 4 rows of one (b,h). Thread (r = t>>4, c = t&15) owns 4 cols.
// 4-deep register ring with prefetch distance 3 to cover L2/DRAM latency.
// ---------------------------------------------------------------------------
__global__ __launch_bounds__(64) void recurrence_kernel(const float* __restrict__ prev_state,
                                                        const float* __restrict__ prev_mom,
                                                        float* __restrict__ out) {
    const int bid = blockIdx.x;
    const int rb  = bid & 15;
    const int h   = (bid >> 4) & 7;
    const int b   = bid >> 7;
    const int t   = threadIdx.x;
    const int r = t >> 4, c = t & 15;
    const int gi = rb * 4 + r;                  // global state row in [0,64)

    float s[4], m[4];
    {
        const size_t off = ((size_t)((b * 8 + h) * 64 + gi)) * 64 + c * 4;
        *(float4*)&s[0] = *(const float4*)(prev_state + off);
        *(float4*)&m[0] = *(const float4*)(prev_mom + off);
    }

    const float* pbh = g_pack + (size_t)((b * 8 + h) * 512) * PSTEP;
    float* ro  = out + ((size_t)(b * 512) * 8 + h) * 64 + gi;
    float* ssq = out + OFF_S + ((size_t)(b * 512) * 8 + h) * 4096 + (size_t)gi * 64 + c * 4;
    float* msq = ssq + (OFF_M - OFF_S);

    // 4-deep prefetch ring (q, k, v, gates)
    float qb[4][4], kb[4][4], vb[4];
    float4 gb[4];
#pragma unroll
    for (int p = 0; p < 3; p++) {
        const float* sp = pbh + p * PSTEP;
        *(float4*)qb[p] = *(const float4*)(sp + c * 4);
        *(float4*)kb[p] = *(const float4*)(sp + 64 + c * 4);
        vb[p] = sp[128 + gi];
        gb[p] = *(const float4*)(sp + 192);
    }

#pragma unroll 4
    for (int l = 0; l < 512; ++l) {
        const int bi = l & 3;
        const int pi = (l + 3) & 3;
        const int pl = (l + 3 < 512) ? (l + 3) : 511;
        const float* sp = pbh + (size_t)pl * PSTEP;
        // prefetch step l+3 into ring slot pi (never collides with bi)
        *(float4*)qb[pi] = *(const float4*)(sp + c * 4);
        *(float4*)kb[pi] = *(const float4*)(sp + 64 + c * 4);
        vb[pi] = sp[128 + gi];
        gb[pi] = *(const float4*)(sp + 192);

        // partial dot products over owned 4 columns
        float pv = 0.f, py = 0.f;
#pragma unroll
        for (int u = 0; u < 4; u++) {
            pv = fmaf(s[u], kb[bi][u], pv);
            py = fmaf(s[u], qb[bi][u], py);
        }
        // reduce over the 16 lanes of this row (pv/py chains interleave)
        pv += __shfl_xor_sync(0xffffffffu, pv, 1);
        py += __shfl_xor_sync(0xffffffffu, py, 1);
        pv += __shfl_xor_sync(0xffffffffu, pv, 2);
        py += __shfl_xor_sync(0xffffffffu, py, 2);
        pv += __shfl_xor_sync(0xffffffffu, pv, 4);
        py += __shfl_xor_sync(0xffffffffu, py, 4);
        pv += __shfl_xor_sync(0xffffffffu, pv, 8);
        py += __shfl_xor_sync(0xffffffffu, py, 8);

        if (c == 0) __stcs(ro + (size_t)l * 512, py);   // readout: PRE-update state

        const float d   = pv - vb[bi];
        const float td  = gb[bi].z * d;
        const float oma = 1.0f - gb[bi].x;
        const float e   = gb[bi].y;
#pragma unroll
        for (int u = 0; u < 4; u++) {
            m[u] = fmaf(e, m[u], -td * kb[bi][u]);   // eta*mom - theta*grad
            s[u] = fmaf(oma, s[u], m[u]);            // (1-alpha)*state + mom
        }

        __stcs((float4*)(ssq + (size_t)l * 32768), *(float4*)&s[0]);
        __stcs((float4*)(msq + (size_t)l * 32768), *(float4*)&m[0]);
    }
}

// ---------------------------------------------------------------------------
// Launch
// ---------------------------------------------------------------------------
extern "C" void kernel_launch(void* const* d_in, const int* in_sizes, int n_in,
                              void* d_out, int out_size) {
    const float* inputs   = (const float*)d_in[0];
    const float* Wq       = (const float*)d_in[1];
    const float* Wk       = (const float*)d_in[2];
    const float* Wv       = (const float*)d_in[3];
    const float* Wp       = (const float*)d_in[4];
    const float* bp       = (const float*)d_in[5];
    const float* prev_st  = (const float*)d_in[6];
    const float* prev_mom = (const float*)d_in[7];
    float* out = (float*)d_out;

    pack_weights_kernel<<<(D_ * NPAD + 255) / 256, 256>>>(Wq, Wk, Wv, Wp);
    sgemm_kernel<<<dim3(NPAD / 128, NROWS / 128), 256>>>(inputs);
    postproc_kernel<<<NROWS, 64>>>(bp);
    recurrence_kernel<<<B_ * H_ * 16, 64>>>(prev_st, prev_mom, out);
}

// round 9
// speedup vs baseline: 1.5853x; 1.5853x over previous
#include <cuda_runtime.h>
#include <cuda_bf16.h>
#include <math.h>

// Problem dims
#define B_ 8
#define L_ 512
#define D_ 512
#define H_ 8
#define DH_ 64
#define NROWS 4096          // B*L
#define NPAD 1664           // 512(q)+512(k)+512(v)+24(p) padded (13*128)
#define KP 1536             // split-GEMM K' = 3*512

// Output layout (concatenated fp32): readout | state_seq | mom_seq
#define OFF_S 2097152UL
#define OFF_M 136314880UL

// Packed per-(b,h) stream: [q(64) | k_norm(64) | v(64) | gates(4)] per step
#define PSTEP 196

// Scratch (static device arrays — no allocation)
__device__ __nv_bfloat16 g_A2[(size_t)NROWS * KP];   // [Ahi | Ahi | Alo] rows
__device__ __nv_bfloat16 g_B2T[(size_t)NPAD * KP];   // n-major: [Whi ; Wlo ; Whi]
__device__ float g_out[(size_t)NROWS * NPAD];        // projections fp32
__device__ float g_pack[(size_t)B_ * H_ * L_ * PSTEP];

// ---------------------------------------------------------------------------
// Kernel 1a: split inputs A[4096,512] -> A2 bf16 [4096,1536]
// sections: [0,512)=hi, [512,1024)=hi, [1024,1536)=lo
// ---------------------------------------------------------------------------
__global__ void pack_a2_kernel(const float* __restrict__ A) {
    int idx = blockIdx.x * blockDim.x + threadIdx.x;
    if (idx >= NROWS * KP) return;
    int m  = idx / KP;
    int kk = idx - m * KP;
    int k  = (kk < 512) ? kk : ((kk < 1024) ? kk - 512 : kk - 1024);
    float x = A[(size_t)m * D_ + k];
    __nv_bfloat16 hi = __float2bfloat16_rn(x);
    if (kk < 1024) {
        g_A2[idx] = hi;
    } else {
        g_A2[idx] = __float2bfloat16_rn(x - __bfloat162float(hi));
    }
}

// ---------------------------------------------------------------------------
// Kernel 1b: split + transpose weights -> B2T bf16 [1664 (n), 1536 (k)]
// column n maps: [0,512)=Wq, [512,1024)=Wk, [1024,1536)=Wv, [1536,1560)=Wp, pad 0
// k-sections: [0,512)=hi, [512,1024)=lo, [1024,1536)=hi
// ---------------------------------------------------------------------------
__global__ void pack_b2t_kernel(const float* __restrict__ Wq,
                                const float* __restrict__ Wk,
                                const float* __restrict__ Wv,
                                const float* __restrict__ Wp) {
    int idx = blockIdx.x * blockDim.x + threadIdx.x;
    if (idx >= NPAD * KP) return;
    int n  = idx / KP;
    int kk = idx - n * KP;
    int k  = (kk < 512) ? kk : ((kk < 1024) ? kk - 512 : kk - 1024);
    float x = 0.f;
    if (n < 512)       x = Wq[k * 512 + n];
    else if (n < 1024) x = Wk[k * 512 + (n - 512)];
    else if (n < 1536) x = Wv[k * 512 + (n - 1024)];
    else if (n < 1560) x = Wp[k * 24 + (n - 1536)];
    __nv_bfloat16 hi = __float2bfloat16_rn(x);
    if (kk >= 512 && kk < 1024) {
        g_B2T[idx] = __float2bfloat16_rn(x - __bfloat162float(hi));
    } else {
        g_B2T[idx] = hi;
    }
}

// ---------------------------------------------------------------------------
// Kernel 2: bf16 tensor-core GEMM  C[4096,1664] = A2[4096,1536] @ B2[1536,1664]
// 128x128 CTA tile, 256 threads (8 warps: 4 m x 2 n), warp tile 32m x 64n,
// mma.m16n8k16 row.col. smem row stride 24 bf16 (conflict-free frag LDS).
// Software pipeline: global loads for k+1 issued before compute on k.
// ---------------------------------------------------------------------------
#define SSTR 24
__global__ __launch_bounds__(256) void mma_gemm_kernel() {
    __shared__ __align__(16) __nv_bfloat16 As[128 * SSTR];
    __shared__ __align__(16) __nv_bfloat16 Bs[128 * SSTR];
    const int tid  = threadIdx.x;
    const int lane = tid & 31;
    const int wid  = tid >> 5;
    const int wm   = wid >> 1;            // 0..3
    const int wn   = wid & 1;             // 0..1
    const int m0   = blockIdx.y * 128;
    const int n0   = blockIdx.x * 128;
    const int r    = lane >> 2;           // 0..7
    const int cq   = (lane & 3) * 2;      // 0,2,4,6

    float acc[2][8][4];
#pragma unroll
    for (int mt = 0; mt < 2; mt++)
#pragma unroll
        for (int nt = 0; nt < 8; nt++)
#pragma unroll
            for (int u = 0; u < 4; u++) acc[mt][nt][u] = 0.f;

    // global loaders: thread t covers row lr, k-half lh (8 bf16 = 16B)
    const int lr = tid >> 1;
    const int lh = (tid & 1) * 8;
    const __nv_bfloat16* gA = g_A2 + (size_t)(m0 + lr) * KP + lh;
    const __nv_bfloat16* gB = g_B2T + (size_t)(n0 + lr) * KP + lh;

    uint4 av = *(const uint4*)gA;
    uint4 bv = *(const uint4*)gB;

    for (int k0 = 0; k0 < KP; k0 += 16) {
        __syncthreads();   // previous compute done reading smem
        *(uint4*)&As[lr * SSTR + lh] = av;
        *(uint4*)&Bs[lr * SSTR + lh] = bv;
        __syncthreads();

        // prefetch next k-tile (overlaps with compute below)
        if (k0 + 16 < KP) {
            av = *(const uint4*)(gA + k0 + 16);
            bv = *(const uint4*)(gB + k0 + 16);
        }

        // B fragments for this warp's 8 n-tiles
        unsigned int bf0[8], bf1[8];
#pragma unroll
        for (int nt = 0; nt < 8; nt++) {
            int n = wn * 64 + nt * 8 + r;
            bf0[nt] = *(const unsigned int*)&Bs[n * SSTR + cq];
            bf1[nt] = *(const unsigned int*)&Bs[n * SSTR + cq + 8];
        }
#pragma unroll
        for (int mt = 0; mt < 2; mt++) {
            int m = wm * 32 + mt * 16 + r;
            unsigned int a0 = *(const unsigned int*)&As[m * SSTR + cq];
            unsigned int a1 = *(const unsigned int*)&As[(m + 8) * SSTR + cq];
            unsigned int a2 = *(const unsigned int*)&As[m * SSTR + cq + 8];
            unsigned int a3 = *(const unsigned int*)&As[(m + 8) * SSTR + cq + 8];
#pragma unroll
            for (int nt = 0; nt < 8; nt++) {
                asm volatile(
                    "mma.sync.aligned.m16n8k16.row.col.f32.bf16.bf16.f32 "
                    "{%0,%1,%2,%3}, {%4,%5,%6,%7}, {%8,%9}, {%0,%1,%2,%3};"
                    : "+f"(acc[mt][nt][0]), "+f"(acc[mt][nt][1]),
                      "+f"(acc[mt][nt][2]), "+f"(acc[mt][nt][3])
                    : "r"(a0), "r"(a1), "r"(a2), "r"(a3),
                      "r"(bf0[nt]), "r"(bf1[nt]));
            }
        }
    }

    // epilogue: c0=C[r][cn], c1=C[r][cn+1], c2=C[r+8][cn], c3=C[r+8][cn+1]
#pragma unroll
    for (int mt = 0; mt < 2; mt++) {
        int row = m0 + wm * 32 + mt * 16 + r;
#pragma unroll
        for (int nt = 0; nt < 8; nt++) {
            int col = n0 + wn * 64 + nt * 8 + cq;
            float* c0 = g_out + (size_t)row * NPAD + col;
            c0[0] = acc[mt][nt][0];
            c0[1] = acc[mt][nt][1];
            float* c2 = c0 + 8 * NPAD;
            c2[0] = acc[mt][nt][2];
            c2[1] = acc[mt][nt][3];
        }
    }
}

// ---------------------------------------------------------------------------
// Kernel 3: postproc — normalize k, compute gates, repack into per-(b,h)
// contiguous stream g_pack[b][h][l] = [q64 | k64 | v64 | a,e,th,0]
// ---------------------------------------------------------------------------
__global__ __launch_bounds__(64) void postproc_kernel(const float* __restrict__ bp) {
    const int row = blockIdx.x;
    const int b = row >> 9, l = row & 511;
    const float* base = g_out + (size_t)row * NPAD;
    const int t  = threadIdx.x;
    const int hh = t >> 3, e8 = t & 7;

    __shared__ float sg[24];
    if (t < 24) {
        float p = base[1536 + t] + bp[t];
        sg[t] = (t < 16) ? (1.0f / (1.0f + expf(-p)))
                         : ((p > 20.f) ? p : log1pf(expf(p)));
    }

    float* dst = g_pack + ((size_t)(b * 8 + hh) * 512 + l) * PSTEP;

    // k: normalize and write
    float kv[8];
    const float* kb = base + 512 + hh * 64 + e8 * 8;
    *(float4*)&kv[0] = *(const float4*)(kb + 0);
    *(float4*)&kv[4] = *(const float4*)(kb + 4);
    float ss = 0.f;
#pragma unroll
    for (int u = 0; u < 8; u++) ss = fmaf(kv[u], kv[u], ss);
    ss += __shfl_xor_sync(0xffffffffu, ss, 1);
    ss += __shfl_xor_sync(0xffffffffu, ss, 2);
    ss += __shfl_xor_sync(0xffffffffu, ss, 4);
    float scale = 1.0f / fmaxf(sqrtf(ss), 1e-12f);
#pragma unroll
    for (int u = 0; u < 8; u++) kv[u] *= scale;
    *(float4*)(dst + 64 + e8 * 8 + 0) = *(float4*)&kv[0];
    *(float4*)(dst + 64 + e8 * 8 + 4) = *(float4*)&kv[4];

    // q copy
    const float* qb = base + hh * 64 + e8 * 8;
    *(float4*)(dst + e8 * 8 + 0) = *(const float4*)(qb + 0);
    *(float4*)(dst + e8 * 8 + 4) = *(const float4*)(qb + 4);

    // v copy
    const float* vb = base + 1024 + hh * 64 + e8 * 8;
    *(float4*)(dst + 128 + e8 * 8 + 0) = *(const float4*)(vb + 0);
    *(float4*)(dst + 128 + e8 * 8 + 4) = *(const float4*)(vb + 4);

    __syncthreads();
    if (e8 < 4) dst[192 + e8] = (e8 < 3) ? sg[e8 * 8 + hh] : 0.f;
}

// ---------------------------------------------------------------------------
// Kernel 4: recurrence (round-5 proven config).
// grid = B*H*16 = 1024 CTAs x 64 threads (2048 warps).
// CTA handles 4 rows of one (b,h). Thread (r = t>>4, c = t&15) owns 4 cols.
// 4-deep register ring with prefetch distance 3 to cover L2/DRAM latency.
// ---------------------------------------------------------------------------
__global__ __launch_bounds__(64) void recurrence_kernel(const float* __restrict__ prev_state,
                                                        const float* __restrict__ prev_mom,
                                                        float* __restrict__ out) {
    const int bid = blockIdx.x;
    const int rb  = bid & 15;
    const int h   = (bid >> 4) & 7;
    const int b   = bid >> 7;
    const int t   = threadIdx.x;
    const int r = t >> 4, c = t & 15;
    const int gi = rb * 4 + r;                  // global state row in [0,64)

    float s[4], m[4];
    {
        const size_t off = ((size_t)((b * 8 + h) * 64 + gi)) * 64 + c * 4;
        *(float4*)&s[0] = *(const float4*)(prev_state + off);
        *(float4*)&m[0] = *(const float4*)(prev_mom + off);
    }

    const float* pbh = g_pack + (size_t)((b * 8 + h) * 512) * PSTEP;
    float* ro  = out + ((size_t)(b * 512) * 8 + h) * 64 + gi;
    float* ssq = out + OFF_S + ((size_t)(b * 512) * 8 + h) * 4096 + (size_t)gi * 64 + c * 4;
    float* msq = ssq + (OFF_M - OFF_S);

    // 4-deep prefetch ring (q, k, v, gates)
    float qb[4][4], kb[4][4], vb[4];
    float4 gb[4];
#pragma unroll
    for (int p = 0; p < 3; p++) {
        const float* sp = pbh + p * PSTEP;
        *(float4*)qb[p] = *(const float4*)(sp + c * 4);
        *(float4*)kb[p] = *(const float4*)(sp + 64 + c * 4);
        vb[p] = sp[128 + gi];
        gb[p] = *(const float4*)(sp + 192);
    }

#pragma unroll 4
    for (int l = 0; l < 512; ++l) {
        const int bi = l & 3;
        const int pi = (l + 3) & 3;
        const int pl = (l + 3 < 512) ? (l + 3) : 511;
        const float* sp = pbh + (size_t)pl * PSTEP;
        // prefetch step l+3 into ring slot pi (never collides with bi)
        *(float4*)qb[pi] = *(const float4*)(sp + c * 4);
        *(float4*)kb[pi] = *(const float4*)(sp + 64 + c * 4);
        vb[pi] = sp[128 + gi];
        gb[pi] = *(const float4*)(sp + 192);

        // partial dot products over owned 4 columns
        float pv = 0.f, py = 0.f;
#pragma unroll
        for (int u = 0; u < 4; u++) {
            pv = fmaf(s[u], kb[bi][u], pv);
            py = fmaf(s[u], qb[bi][u], py);
        }
        // reduce over the 16 lanes of this row (pv/py chains interleave)
        pv += __shfl_xor_sync(0xffffffffu, pv, 1);
        py += __shfl_xor_sync(0xffffffffu, py, 1);
        pv += __shfl_xor_sync(0xffffffffu, pv, 2);
        py += __shfl_xor_sync(0xffffffffu, py, 2);
        pv += __shfl_xor_sync(0xffffffffu, pv, 4);
        py += __shfl_xor_sync(0xffffffffu, py, 4);
        pv += __shfl_xor_sync(0xffffffffu, pv, 8);
        py += __shfl_xor_sync(0xffffffffu, py, 8);

        if (c == 0) __stcs(ro + (size_t)l * 512, py);   // readout: PRE-update state

        const float d   = pv - vb[bi];
        const float td  = gb[bi].z * d;
        const float oma = 1.0f - gb[bi].x;
        const float e   = gb[bi].y;
#pragma unroll
        for (int u = 0; u < 4; u++) {
            m[u] = fmaf(e, m[u], -td * kb[bi][u]);   // eta*mom - theta*grad
            s[u] = fmaf(oma, s[u], m[u]);            // (1-alpha)*state + mom
        }

        __stcs((float4*)(ssq + (size_t)l * 32768), *(float4*)&s[0]);
        __stcs((float4*)(msq + (size_t)l * 32768), *(float4*)&m[0]);
    }
}

// ---------------------------------------------------------------------------
// Launch
// ---------------------------------------------------------------------------
extern "C" void kernel_launch(void* const* d_in, const int* in_sizes, int n_in,
                              void* d_out, int out_size) {
    const float* inputs   = (const float*)d_in[0];
    const float* Wq       = (const float*)d_in[1];
    const float* Wk       = (const float*)d_in[2];
    const float* Wv       = (const float*)d_in[3];
    const float* Wp       = (const float*)d_in[4];
    const float* bp       = (const float*)d_in[5];
    const float* prev_st  = (const float*)d_in[6];
    const float* prev_mom = (const float*)d_in[7];
    float* out = (float*)d_out;

    pack_a2_kernel<<<(NROWS * KP + 255) / 256, 256>>>(inputs);
    pack_b2t_kernel<<<(NPAD * KP + 255) / 256, 256>>>(Wq, Wk, Wv, Wp);
    mma_gemm_kernel<<<dim3(NPAD / 128, NROWS / 128), 256>>>();
    postproc_kernel<<<NROWS, 64>>>(bp);
    recurrence_kernel<<<B_ * H_ * 16, 64>>>(prev_st, prev_mom, out);
}